// round 12
// baseline (speedup 1.0000x reference)
#include <cuda_runtime.h>
#include <cuda_fp16.h>
#include <math.h>

// Fixed problem shape: B=16, H=W=512
#define Bn 16
#define Hn 512
#define Wn 512
#define TILE 32
#define FD  34        // feat rows/cols (halo 1)
#define FDPH 40       // feat pitch in halves
#define ID  36        // input tile rows/cols (halo 2)
#define IN_PLANE_H (ID*ID)        // 1296 halves per channel
#define IN_HALVES  (3*IN_PLANE_H) // 3888
#define FEAT_HALVES (16*FD*FDPH)  // 21760

// smem floats: in(fp16) 1944 | feat(fp16) 10880 | w1t 432 | b1 16 | b2 18 | wk 9
#define SMEM_FLOATS (IN_HALVES/2 + FEAT_HALVES/2 + 432 + 16 + 18 + 9)

typedef unsigned long long ull;

__device__ __forceinline__ ull pack2(float lo, float hi) {
    ull r; asm("mov.b64 %0, {%1, %2};" : "=l"(r) : "f"(lo), "f"(hi)); return r;
}
__device__ __forceinline__ void unpack2(ull v, float& lo, float& hi) {
    asm("mov.b64 {%0, %1}, %2;" : "=f"(lo), "=f"(hi) : "l"(v));
}
__device__ __forceinline__ void ffma2(ull& d, ull a, ull b) {
    asm("fma.rn.f32x2 %0, %1, %2, %0;" : "+l"(d) : "l"(a), "l"(b));
}
__device__ __forceinline__ ull fma2v(ull a, ull b, ull c) {
    ull r; asm("fma.rn.f32x2 %0, %1, %2, %3;" : "=l"(r) : "l"(a), "l"(b), "l"(c)); return r;
}
__device__ __forceinline__ ull mul2(ull a, ull b) {
    ull r; asm("mul.rn.f32x2 %0, %1, %2;" : "=l"(r) : "l"(a), "l"(b)); return r;
}

// GELU on 2 packed fp32 lanes: x * sigmoid(1.59577x + 0.0713548x^3)
__device__ __forceinline__ ull gelu2(ull x2) {
    ull xsq = mul2(x2, x2);
    ull t = fma2v(xsq, pack2(0.07135481627f, 0.07135481627f),
                        pack2(1.59576912161f, 1.59576912161f));
    ull y = mul2(x2, t);
    ull z = mul2(y, pack2(-1.44269504089f, -1.44269504089f));
    float zlo, zhi; unpack2(z, zlo, zhi);
    float elo, ehi;
    asm("ex2.approx.f32 %0, %1;" : "=f"(elo) : "f"(zlo));
    asm("ex2.approx.f32 %0, %1;" : "=f"(ehi) : "f"(zhi));
    float dlo = 1.0f + elo, dhi = 1.0f + ehi;
    float slo, shi;
    asm("rcp.approx.f32 %0, %1;" : "=f"(slo) : "f"(dlo));
    asm("rcp.approx.f32 %0, %1;" : "=f"(shi) : "f"(dhi));
    return mul2(x2, pack2(slo, shi));
}

__global__ __launch_bounds__(256, 4)
void fused_residual_advection(const float* __restrict__ pm25,
                              const float* __restrict__ wind,
                              const float* __restrict__ topo,
                              const float* __restrict__ w1,
                              const float* __restrict__ b1,
                              const float* __restrict__ w2,
                              const float* __restrict__ b2,
                              const float* __restrict__ wk,
                              float* __restrict__ out)
{
    extern __shared__ float smem[];
    __half* s_in_h   = (__half*)smem;                    // [3][36][36] fp16
    __half* s_feat_h = s_in_h + IN_HALVES;               // [16][34][40] fp16
    float*  s_w1t    = smem + IN_HALVES/2 + FEAT_HALVES/2;  // [27][16]
    float*  s_b1     = s_w1t + 432;
    float*  s_b2     = s_b1 + 16;
    float*  s_wk     = s_b2 + 18;

    const int tid = threadIdx.x;
    const int b   = blockIdx.z;
    const int ty0 = blockIdx.y * TILE;
    const int tx0 = blockIdx.x * TILE;

    for (int i = tid; i < 432; i += 256) {
        int o = i / 27, j = i - o * 27;
        s_w1t[j*16 + o] = w1[i];
    }
    if (tid < 16) s_b1[tid] = b1[tid];
    else if (tid >= 32 && tid < 50) s_b2[tid - 32] = b2[tid - 32];
    else if (tid >= 64 && tid < 73) s_wk[tid - 64] = wk[tid - 64];

    // ---- stage input as fp16, zero-padded ----
    const int gy0 = ty0 - 2, gx0 = tx0 - 2;
    const float* wind0 = wind + (size_t)b * 2 * Hn * Wn;
    const float* wind1 = wind0 + Hn * Wn;
    const float* topob = topo + (size_t)b * Hn * Wn;
    for (int i = tid; i < IN_HALVES; i += 256) {
        int c   = i / IN_PLANE_H;
        int rem = i - c * IN_PLANE_H;
        int ly  = rem / ID, lx = rem - ly * ID;
        int gy = gy0 + ly, gx = gx0 + lx;
        float v = 0.f;
        if ((unsigned)gy < Hn && (unsigned)gx < Wn) {
            const float* src = (c == 0) ? wind0 : ((c == 1) ? wind1 : topob);
            v = __ldg(src + (size_t)gy * Wn + gx);
        }
        s_in_h[i] = __float2half_rn(v);
    }
    __syncthreads();

    // ---- phase 2: conv1 + GELU -> fp16 feat ----
    // Adjacent pixel pairs (fx even); window held as 18 half2 regs (9 LDS.32);
    // per-(c,ky) cvt + dup-pack; channel-halves keep acc at 8 ull.
    {
        const int npairs = (FD*FD)/2;   // 578
        for (int pi = tid; pi < npairs; pi += 256) {
            const int lin = 2*pi;
            const int fy = lin / FD, fx = lin - fy * FD;   // fx even
            const bool okA = ((unsigned)(ty0 - 1 + fy) < Hn) & ((unsigned)(tx0 - 1 + fx)     < Wn);
            const bool okB = ((unsigned)(ty0 - 1 + fy) < Hn) & ((unsigned)(tx0 - 1 + fx + 1) < Wn);

            // window: 3 ch x 3 rows x 4 cols as half2 (4B-aligned: fx even)
            __half2 hw[3][3][2];
            #pragma unroll
            for (int c = 0; c < 3; c++)
                #pragma unroll
                for (int ky = 0; ky < 3; ky++) {
                    const __half* rp = &s_in_h[c*IN_PLANE_H + (fy + ky)*ID + fx];
                    hw[c][ky][0] = *(const __half2*)rp;
                    hw[c][ky][1] = *(const __half2*)(rp + 2);
                }

            const int po = fy*FDPH + fx;
            #pragma unroll
            for (int h = 0; h < 2; h++) {
                ull aA[4], aB[4];
                #pragma unroll
                for (int p = 0; p < 4; p++) {
                    const ull bp = *(const ull*)&s_b1[2*(4*h + p)];
                    aA[p] = bp; aB[p] = bp;
                }

                #pragma unroll
                for (int c = 0; c < 3; c++) {
                    #pragma unroll
                    for (int ky = 0; ky < 3; ky++) {
                        const float2 e01 = __half22float2(hw[c][ky][0]);
                        const float2 e23 = __half22float2(hw[c][ky][1]);
                        ull d[4];
                        d[0] = pack2(e01.x, e01.x);
                        d[1] = pack2(e01.y, e01.y);
                        d[2] = pack2(e23.x, e23.x);
                        d[3] = pack2(e23.y, e23.y);
                        #pragma unroll
                        for (int kx = 0; kx < 3; kx++) {
                            const int j = c*9 + ky*3 + kx;
                            const ulonglong2* wp = (const ulonglong2*)&s_w1t[j*16 + h*8];
                            const ulonglong2 w01 = wp[0], w23 = wp[1];
                            ffma2(aA[0], d[kx],   w01.x); ffma2(aA[1], d[kx],   w01.y);
                            ffma2(aA[2], d[kx],   w23.x); ffma2(aA[3], d[kx],   w23.y);
                            ffma2(aB[0], d[kx+1], w01.x); ffma2(aB[1], d[kx+1], w01.y);
                            ffma2(aB[2], d[kx+1], w23.x); ffma2(aB[3], d[kx+1], w23.y);
                        }
                    }
                }

                #pragma unroll
                for (int p = 0; p < 4; p++) {
                    const int ch = 8*h + 2*p;
                    float g0A, g1A, g0B, g1B;
                    unpack2(gelu2(aA[p]), g0A, g1A);
                    unpack2(gelu2(aB[p]), g0B, g1B);
                    g0A = okA ? g0A : 0.f; g1A = okA ? g1A : 0.f;
                    g0B = okB ? g0B : 0.f; g1B = okB ? g1B : 0.f;
                    *(__half2*)&s_feat_h[ch    *FD*FDPH + po] = __floats2half2_rn(g0A, g0B);
                    *(__half2*)&s_feat_h[(ch+1)*FD*FDPH + po] = __floats2half2_rn(g1A, g1B);
                }
            }
        }
    }
    __syncthreads();

    // ---- phase 3: conv2 (active taps) + bilinear; f32x2 x-pairs, fp16 feat ----
    const int x0p = (tid & 7) * 4;
    const int row = tid >> 3;
    const float* img = pm25 + (size_t)b * Hn * Wn;
    float* s_wdup = smem;   // overlays dead fp16 input region; 576 floats = 2304B < 7776B

    float acc[4] = {0.f, 0.f, 0.f, 0.f};

    for (int k = 0; k < 9; k++) {
        const float wkv = s_wk[k];
        if (wkv == 0.0f) continue;          // uniform across block, value-exact
        const int kdy = k / 3 - 1, kdx = k - (k/3)*3 - 1;

        __syncthreads();
        for (int i = tid; i < 144; i += 256) {
            const int c = i / 9, j = i - c * 9;
            const float wy = __ldg(&w2[(size_t)(2*k)    *144 + c*9 + j]);
            const float wx = __ldg(&w2[(size_t)(2*k + 1)*144 + c*9 + j]);
            float* p = &s_wdup[(j*16 + c)*4];
            p[0] = wy; p[1] = wy; p[2] = wx; p[3] = wx;
        }
        __syncthreads();

        const float bdy = s_b2[2*k], bdx = s_b2[2*k + 1];
        ull ady0 = pack2(bdy, bdy), ady1 = ady0;
        ull adx0 = pack2(bdx, bdx), adx1 = adx0;

        #pragma unroll
        for (int c = 0; c < 16; c++) {
            const __half* fb = s_feat_h + c*FD*FDPH + row*FDPH + x0p;
            #pragma unroll
            for (int ky = 0; ky < 3; ky++) {
                const __half* rp = fb + ky*FDPH;
                const uint2 q = *(const uint2*)(rp);              // h0..h3
                const __half2 h01 = *(const __half2*)&q.x;
                const __half2 h23 = *(const __half2*)&q.y;
                const __half2 h45 = *(const __half2*)(rp + 4);    // h4,h5
                const float2 e0 = __half22float2(h01);
                const float2 e1 = __half22float2(h23);
                const float2 e2 = __half22float2(h45);
                const ull P0 = pack2(e0.x, e0.y);
                const ull P1 = pack2(e0.y, e1.x);
                const ull P2 = pack2(e1.x, e1.y);
                const ull P3 = pack2(e1.y, e2.x);
                const ull P4 = pack2(e2.x, e2.y);

                const ulonglong2 wv0 = *(const ulonglong2*)&s_wdup[((ky*3+0)*16 + c)*4];
                const ulonglong2 wv1 = *(const ulonglong2*)&s_wdup[((ky*3+1)*16 + c)*4];
                const ulonglong2 wv2 = *(const ulonglong2*)&s_wdup[((ky*3+2)*16 + c)*4];
                ffma2(ady0, P0, wv0.x); ffma2(ady1, P2, wv0.x);
                ffma2(adx0, P0, wv0.y); ffma2(adx1, P2, wv0.y);
                ffma2(ady0, P1, wv1.x); ffma2(ady1, P3, wv1.x);
                ffma2(adx0, P1, wv1.y); ffma2(adx1, P3, wv1.y);
                ffma2(ady0, P2, wv2.x); ffma2(ady1, P4, wv2.x);
                ffma2(adx0, P2, wv2.y); ffma2(adx1, P4, wv2.y);
            }
        }

        float dyv[4], dxv[4];
        unpack2(ady0, dyv[0], dyv[1]); unpack2(ady1, dyv[2], dyv[3]);
        unpack2(adx0, dxv[0], dxv[1]); unpack2(adx1, dxv[2], dxv[3]);

        #pragma unroll
        for (int i = 0; i < 4; i++) {
            const int gy = ty0 + row;
            const int gx = tx0 + x0p + i;
            const float py = (float)(gy + kdy) + dyv[i];
            const float px = (float)(gx + kdx) + dxv[i];
            const float y0f = floorf(py), x0f = floorf(px);
            const float wy = py - y0f, wx = px - x0f;
            const int yy0 = (int)y0f, xx0 = (int)x0f;
            const int yy1 = yy0 + 1,  xx1 = xx0 + 1;
            const bool okY0 = (yy0 >= 0) & (yy0 < Hn);
            const bool okY1 = (yy1 >= 0) & (yy1 < Hn);
            const bool okX0 = (xx0 >= 0) & (xx0 < Wn);
            const bool okX1 = (xx1 >= 0) & (xx1 < Wn);
            const float v00 = (okY0 & okX0) ? __ldg(img + (size_t)yy0*Wn + xx0) : 0.f;
            const float v01 = (okY0 & okX1) ? __ldg(img + (size_t)yy0*Wn + xx1) : 0.f;
            const float v10 = (okY1 & okX0) ? __ldg(img + (size_t)yy1*Wn + xx0) : 0.f;
            const float v11 = (okY1 & okX1) ? __ldg(img + (size_t)yy1*Wn + xx1) : 0.f;
            const float s = v00*(1.f - wy)*(1.f - wx) + v01*(1.f - wy)*wx
                          + v10*wy*(1.f - wx)         + v11*wy*wx;
            acc[i] = fmaf(wkv, s, acc[i]);
        }
    }

    float4 o4; o4.x = acc[0]; o4.y = acc[1]; o4.z = acc[2]; o4.w = acc[3];
    *(float4*)&out[(size_t)b * Hn * Wn + (size_t)(ty0 + row) * Wn + (tx0 + x0p)] = o4;
}

extern "C" void kernel_launch(void* const* d_in, const int* in_sizes, int n_in,
                              void* d_out, int out_size)
{
    const float* pm25 = (const float*)d_in[0];
    const float* wind = (const float*)d_in[1];
    const float* topo = (const float*)d_in[2];
    const float* w1   = (const float*)d_in[3];
    const float* b1   = (const float*)d_in[4];
    const float* w2   = (const float*)d_in[5];
    const float* b2   = (const float*)d_in[6];
    const float* wk   = (const float*)d_in[7];
    float* out = (float*)d_out;

    const size_t smem_bytes = (size_t)SMEM_FLOATS * sizeof(float);
    cudaFuncSetAttribute(fused_residual_advection,
                         cudaFuncAttributeMaxDynamicSharedMemorySize,
                         (int)smem_bytes);

    dim3 grid(Wn / TILE, Hn / TILE, Bn);
    fused_residual_advection<<<grid, 256, smem_bytes>>>(
        pm25, wind, topo, w1, b1, w2, b2, wk, out);
}

// round 13
// speedup vs baseline: 1.1605x; 1.1605x over previous
#include <cuda_runtime.h>
#include <cuda_fp16.h>
#include <math.h>

// Fixed problem shape: B=16, H=W=512
#define Bn 16
#define Hn 512
#define Wn 512
#define TILE 32
#define FD  34       // feat rows/cols (halo 1)
#define FDPH 40      // feat pitch in halves (80B rows, 8B-aligned accesses)
#define ID  36       // input tile with halo 2

// smem floats: s_in 3888 | feat(fp16) 10880 | w1t 432 | b1 16 | b2 18 | wk 9
#define SMEM_FLOATS (3*ID*ID + (16*FD*FDPH)/2 + 432 + 16 + 18 + 9)

typedef unsigned long long ull;

__device__ __forceinline__ ull pack2(float lo, float hi) {
    ull r; asm("mov.b64 %0, {%1, %2};" : "=l"(r) : "f"(lo), "f"(hi)); return r;
}
__device__ __forceinline__ void unpack2(ull v, float& lo, float& hi) {
    asm("mov.b64 {%0, %1}, %2;" : "=f"(lo), "=f"(hi) : "l"(v));
}
__device__ __forceinline__ void ffma2(ull& d, ull a, ull b) {
    asm("fma.rn.f32x2 %0, %1, %2, %0;" : "+l"(d) : "l"(a), "l"(b));
}
__device__ __forceinline__ ull fma2v(ull a, ull b, ull c) {
    ull r; asm("fma.rn.f32x2 %0, %1, %2, %3;" : "=l"(r) : "l"(a), "l"(b), "l"(c)); return r;
}
__device__ __forceinline__ ull mul2(ull a, ull b) {
    ull r; asm("mul.rn.f32x2 %0, %1, %2;" : "=l"(r) : "l"(a), "l"(b)); return r;
}

// GELU on 2 packed fp32 lanes: x * sigmoid(1.59577x + 0.0713548x^3)
__device__ __forceinline__ ull gelu2(ull x2) {
    ull xsq = mul2(x2, x2);
    ull t = fma2v(xsq, pack2(0.07135481627f, 0.07135481627f),
                        pack2(1.59576912161f, 1.59576912161f));
    ull y = mul2(x2, t);
    ull z = mul2(y, pack2(-1.44269504089f, -1.44269504089f));
    float zlo, zhi; unpack2(z, zlo, zhi);
    float elo, ehi;
    asm("ex2.approx.f32 %0, %1;" : "=f"(elo) : "f"(zlo));
    asm("ex2.approx.f32 %0, %1;" : "=f"(ehi) : "f"(zhi));
    float dlo = 1.0f + elo, dhi = 1.0f + ehi;
    float slo, shi;
    asm("rcp.approx.f32 %0, %1;" : "=f"(slo) : "f"(dlo));
    asm("rcp.approx.f32 %0, %1;" : "=f"(shi) : "f"(dhi));
    return mul2(x2, pack2(slo, shi));
}

__global__ __launch_bounds__(256, 3)
void fused_residual_advection(const float* __restrict__ pm25,
                              const float* __restrict__ wind,
                              const float* __restrict__ topo,
                              const float* __restrict__ w1,
                              const float* __restrict__ b1,
                              const float* __restrict__ w2,
                              const float* __restrict__ b2,
                              const float* __restrict__ wk,
                              float* __restrict__ out)
{
    extern __shared__ float smem[];
    float*  s_in     = smem;                             // [3][36][36]; phase3: dup-w table
    __half* s_feat_h = (__half*)(s_in + 3*ID*ID);        // [16][34][40] halves
    float*  s_w1t    = s_in + 3*ID*ID + (16*FD*FDPH)/2;  // [27][16]
    float*  s_b1     = s_w1t + 432;
    float*  s_b2     = s_b1 + 16;
    float*  s_wk     = s_b2 + 18;

    const int tid = threadIdx.x;
    const int b   = blockIdx.z;
    const int ty0 = blockIdx.y * TILE;
    const int tx0 = blockIdx.x * TILE;

    for (int i = tid; i < 432; i += 256) {
        int o = i / 27, j = i - o * 27;
        s_w1t[j*16 + o] = w1[i];
    }
    if (tid < 16) s_b1[tid] = b1[tid];
    else if (tid >= 32 && tid < 50) s_b2[tid - 32] = b2[tid - 32];
    else if (tid >= 64 && tid < 73) s_wk[tid - 64] = wk[tid - 64];

    const int gy0 = ty0 - 2, gx0 = tx0 - 2;
    const float* wind0 = wind + (size_t)b * 2 * Hn * Wn;
    const float* wind1 = wind0 + Hn * Wn;
    const float* topob = topo + (size_t)b * Hn * Wn;
    for (int i = tid; i < ID*ID; i += 256) {
        int ly = i / ID, lx = i - ly * ID;
        int gy = gy0 + ly, gx = gx0 + lx;
        bool ok = (gy >= 0) & (gy < Hn) & (gx >= 0) & (gx < Wn);
        size_t gidx = (size_t)gy * Wn + gx;
        s_in[0*ID*ID + i] = ok ? __ldg(wind0 + gidx) : 0.f;
        s_in[1*ID*ID + i] = ok ? __ldg(wind1 + gidx) : 0.f;
        s_in[2*ID*ID + i] = ok ? __ldg(topob + gidx) : 0.f;
    }
    __syncthreads();

    // ---- phase 2: conv1 + GELU -> fp16 feat ----
    // Balanced: 512 adjacent-pairs (2 iters/thread) + 132 leftover pixels
    // as singles across 132 threads (halves the tail critical path).
    {
        ull b1p[8];
        #pragma unroll
        for (int p = 0; p < 8; p++) b1p[p] = pack2(s_b1[2*p], s_b1[2*p + 1]);

        // main: pairs 0..511 -> pixels 0..1023
        #pragma unroll
        for (int it = 0; it < 2; it++) {
            const int pi = tid + it*256;
            const int lin = 2*pi;
            const int fy = lin / FD, fx = lin - fy * FD;   // fx even
            const bool okA = ((unsigned)(ty0 - 1 + fy) < Hn) & ((unsigned)(tx0 - 1 + fx)     < Wn);
            const bool okB = ((unsigned)(ty0 - 1 + fy) < Hn) & ((unsigned)(tx0 - 1 + fx + 1) < Wn);

            float r[3][3][4];
            #pragma unroll
            for (int c = 0; c < 3; c++)
                #pragma unroll
                for (int ky = 0; ky < 3; ky++) {
                    const float* rp = &s_in[c*ID*ID + (fy + ky)*ID + fx];
                    const float2 q0 = *(const float2*)rp;
                    const float2 q1 = *(const float2*)(rp + 2);
                    r[c][ky][0] = q0.x; r[c][ky][1] = q0.y;
                    r[c][ky][2] = q1.x; r[c][ky][3] = q1.y;
                }

            const int po = fy*FDPH + fx;
            #pragma unroll
            for (int h = 0; h < 2; h++) {
                ull aA[4], aB[4];
                #pragma unroll
                for (int p = 0; p < 4; p++) { aA[p] = b1p[4*h + p]; aB[p] = b1p[4*h + p]; }

                #pragma unroll
                for (int j = 0; j < 27; j++) {
                    const int c  = j / 9;
                    const int r9 = j - c * 9;
                    const int ky = r9 / 3, kx = r9 - ky * 3;
                    const ull vA2 = pack2(r[c][ky][kx],     r[c][ky][kx]);
                    const ull vB2 = pack2(r[c][ky][kx + 1], r[c][ky][kx + 1]);
                    const ulonglong2* wp = (const ulonglong2*)&s_w1t[j*16 + h*8];
                    const ulonglong2 w01 = wp[0], w23 = wp[1];
                    ffma2(aA[0], vA2, w01.x); ffma2(aA[1], vA2, w01.y);
                    ffma2(aA[2], vA2, w23.x); ffma2(aA[3], vA2, w23.y);
                    ffma2(aB[0], vB2, w01.x); ffma2(aB[1], vB2, w01.y);
                    ffma2(aB[2], vB2, w23.x); ffma2(aB[3], vB2, w23.y);
                }

                #pragma unroll
                for (int p = 0; p < 4; p++) {
                    const int ch = 8*h + 2*p;
                    float g0A, g1A, g0B, g1B;
                    unpack2(gelu2(aA[p]), g0A, g1A);
                    unpack2(gelu2(aB[p]), g0B, g1B);
                    g0A = okA ? g0A : 0.f; g1A = okA ? g1A : 0.f;
                    g0B = okB ? g0B : 0.f; g1B = okB ? g1B : 0.f;
                    *(__half2*)&s_feat_h[ch    *FD*FDPH + po] = __floats2half2_rn(g0A, g0B);
                    *(__half2*)&s_feat_h[(ch+1)*FD*FDPH + po] = __floats2half2_rn(g1A, g1B);
                }
            }
        }

        // tail: pixels 1024..1155 as singles over threads 0..131
        if (tid < 132) {
            const int lin = 1024 + tid;
            const int fy = lin / FD, fx = lin - fy * FD;
            const bool ok = ((unsigned)(ty0 - 1 + fy) < Hn) & ((unsigned)(tx0 - 1 + fx) < Wn);

            float r[3][3][3];
            #pragma unroll
            for (int c = 0; c < 3; c++)
                #pragma unroll
                for (int ky = 0; ky < 3; ky++) {
                    const float* rp = &s_in[c*ID*ID + (fy + ky)*ID + fx];
                    r[c][ky][0] = rp[0]; r[c][ky][1] = rp[1]; r[c][ky][2] = rp[2];
                }

            const int po = fy*FDPH + fx;
            #pragma unroll
            for (int h = 0; h < 2; h++) {
                ull aA[4];
                #pragma unroll
                for (int p = 0; p < 4; p++) aA[p] = b1p[4*h + p];
                #pragma unroll
                for (int j = 0; j < 27; j++) {
                    const int c  = j / 9;
                    const int r9 = j - c * 9;
                    const int ky = r9 / 3, kx = r9 - ky * 3;
                    const ull v2 = pack2(r[c][ky][kx], r[c][ky][kx]);
                    const ulonglong2* wp = (const ulonglong2*)&s_w1t[j*16 + h*8];
                    const ulonglong2 w01 = wp[0], w23 = wp[1];
                    ffma2(aA[0], v2, w01.x); ffma2(aA[1], v2, w01.y);
                    ffma2(aA[2], v2, w23.x); ffma2(aA[3], v2, w23.y);
                }
                #pragma unroll
                for (int p = 0; p < 4; p++) {
                    const int ch = 8*h + 2*p;
                    float g0, g1;
                    unpack2(gelu2(aA[p]), g0, g1);
                    s_feat_h[ch    *FD*FDPH + po] = __float2half_rn(ok ? g0 : 0.f);
                    s_feat_h[(ch+1)*FD*FDPH + po] = __float2half_rn(ok ? g1 : 0.f);
                }
            }
        }
    }
    __syncthreads();

    // ---- phase 3: conv2 (active taps) + bilinear; f32x2 x-pairs, fp16 feat ----
    const int x0  = (tid & 7) * 4;
    const int row = tid >> 3;
    const float* img = pm25 + (size_t)b * Hn * Wn;
    float* s_wdup = s_in;    // dead region; [j][c]{wdy,wdy,wdx,wdx} = 576 floats

    float acc[4] = {0.f, 0.f, 0.f, 0.f};
    bool first_tap = true;

    for (int k = 0; k < 9; k++) {
        const float wkv = s_wk[k];
        if (wkv == 0.0f) continue;          // uniform across block, value-exact
        const int kdy = k / 3 - 1, kdx = k - (k/3)*3 - 1;

        if (!first_tap) __syncthreads();    // protect s_wdup rebuild only
        first_tap = false;
        for (int i = tid; i < 144; i += 256) {
            const int c = i / 9, j = i - c * 9;
            const float wy = __ldg(&w2[(size_t)(2*k)    *144 + c*9 + j]);
            const float wx = __ldg(&w2[(size_t)(2*k + 1)*144 + c*9 + j]);
            float* p = &s_wdup[(j*16 + c)*4];
            p[0] = wy; p[1] = wy; p[2] = wx; p[3] = wx;
        }
        __syncthreads();

        const float bdy = s_b2[2*k], bdx = s_b2[2*k + 1];
        ull ady0 = pack2(bdy, bdy), ady1 = ady0;
        ull adx0 = pack2(bdx, bdx), adx1 = adx0;

        #pragma unroll
        for (int c = 0; c < 16; c++) {
            const __half* fb = s_feat_h + c*FD*FDPH + row*FDPH + x0;
            #pragma unroll
            for (int ky = 0; ky < 3; ky++) {
                const __half* rp = fb + ky*FDPH;
                const uint2 q = *(const uint2*)(rp);              // h0..h3
                const __half2 h01 = *(const __half2*)&q.x;
                const __half2 h23 = *(const __half2*)&q.y;
                const __half2 h45 = *(const __half2*)(rp + 4);    // h4,h5
                const float2 e0 = __half22float2(h01);
                const float2 e1 = __half22float2(h23);
                const float2 e2 = __half22float2(h45);
                const ull P0 = pack2(e0.x, e0.y);
                const ull P1 = pack2(e0.y, e1.x);
                const ull P2 = pack2(e1.x, e1.y);
                const ull P3 = pack2(e1.y, e2.x);
                const ull P4 = pack2(e2.x, e2.y);

                const ulonglong2 wv0 = *(const ulonglong2*)&s_wdup[((ky*3+0)*16 + c)*4];
                const ulonglong2 wv1 = *(const ulonglong2*)&s_wdup[((ky*3+1)*16 + c)*4];
                const ulonglong2 wv2 = *(const ulonglong2*)&s_wdup[((ky*3+2)*16 + c)*4];
                ffma2(ady0, P0, wv0.x); ffma2(ady1, P2, wv0.x);
                ffma2(adx0, P0, wv0.y); ffma2(adx1, P2, wv0.y);
                ffma2(ady0, P1, wv1.x); ffma2(ady1, P3, wv1.x);
                ffma2(adx0, P1, wv1.y); ffma2(adx1, P3, wv1.y);
                ffma2(ady0, P2, wv2.x); ffma2(ady1, P4, wv2.x);
                ffma2(adx0, P2, wv2.y); ffma2(adx1, P4, wv2.y);
            }
        }

        float dyv[4], dxv[4];
        unpack2(ady0, dyv[0], dyv[1]); unpack2(ady1, dyv[2], dyv[3]);
        unpack2(adx0, dxv[0], dxv[1]); unpack2(adx1, dxv[2], dxv[3]);

        #pragma unroll
        for (int i = 0; i < 4; i++) {
            const int gy = ty0 + row;
            const int gx = tx0 + x0 + i;
            const float py = (float)(gy + kdy) + dyv[i];
            const float px = (float)(gx + kdx) + dxv[i];
            const float y0f = floorf(py), x0f = floorf(px);
            const float wy = py - y0f, wx = px - x0f;
            const int yy0 = (int)y0f, xx0 = (int)x0f;
            const int yy1 = yy0 + 1,  xx1 = xx0 + 1;
            const bool okY0 = (yy0 >= 0) & (yy0 < Hn);
            const bool okY1 = (yy1 >= 0) & (yy1 < Hn);
            const bool okX0 = (xx0 >= 0) & (xx0 < Wn);
            const bool okX1 = (xx1 >= 0) & (xx1 < Wn);
            const float v00 = (okY0 & okX0) ? __ldg(img + (size_t)yy0*Wn + xx0) : 0.f;
            const float v01 = (okY0 & okX1) ? __ldg(img + (size_t)yy0*Wn + xx1) : 0.f;
            const float v10 = (okY1 & okX0) ? __ldg(img + (size_t)yy1*Wn + xx0) : 0.f;
            const float v11 = (okY1 & okX1) ? __ldg(img + (size_t)yy1*Wn + xx1) : 0.f;
            const float s = v00*(1.f - wy)*(1.f - wx) + v01*(1.f - wy)*wx
                          + v10*wy*(1.f - wx)         + v11*wy*wx;
            acc[i] = fmaf(wkv, s, acc[i]);
        }
    }

    float4 o4; o4.x = acc[0]; o4.y = acc[1]; o4.z = acc[2]; o4.w = acc[3];
    *(float4*)&out[(size_t)b * Hn * Wn + (size_t)(ty0 + row) * Wn + (tx0 + x0)] = o4;
}

extern "C" void kernel_launch(void* const* d_in, const int* in_sizes, int n_in,
                              void* d_out, int out_size)
{
    const float* pm25 = (const float*)d_in[0];
    const float* wind = (const float*)d_in[1];
    const float* topo = (const float*)d_in[2];
    const float* w1   = (const float*)d_in[3];
    const float* b1   = (const float*)d_in[4];
    const float* w2   = (const float*)d_in[5];
    const float* b2   = (const float*)d_in[6];
    const float* wk   = (const float*)d_in[7];
    float* out = (float*)d_out;

    const size_t smem_bytes = (size_t)SMEM_FLOATS * sizeof(float);
    cudaFuncSetAttribute(fused_residual_advection,
                         cudaFuncAttributeMaxDynamicSharedMemorySize,
                         (int)smem_bytes);

    dim3 grid(Wn / TILE, Hn / TILE, Bn);
    fused_residual_advection<<<grid, 256, smem_bytes>>>(
        pm25, wind, topo, w1, b1, w2, b2, wk, out);
}

// round 14
// speedup vs baseline: 1.1743x; 1.0119x over previous
#include <cuda_runtime.h>
#include <cuda_fp16.h>
#include <math.h>

// Fixed problem shape: B=16, H=W=512
#define Bn 16
#define Hn 512
#define Wn 512
#define TILE 32
#define FD  34       // feat rows/cols (halo 1)
#define FDPH 40      // feat pitch in halves (80B rows, 8B-aligned accesses)
#define ID  36       // input tile with halo 2

// smem floats: s_in 3888 | feat(fp16) 10880 | w1t 432 | b1 16 | b2 18 | wk 9
#define SMEM_FLOATS (3*ID*ID + (16*FD*FDPH)/2 + 432 + 16 + 18 + 9)

typedef unsigned long long ull;

__device__ __forceinline__ ull pack2(float lo, float hi) {
    ull r; asm("mov.b64 %0, {%1, %2};" : "=l"(r) : "f"(lo), "f"(hi)); return r;
}
__device__ __forceinline__ void unpack2(ull v, float& lo, float& hi) {
    asm("mov.b64 {%0, %1}, %2;" : "=f"(lo), "=f"(hi) : "l"(v));
}
__device__ __forceinline__ void ffma2(ull& d, ull a, ull b) {
    asm("fma.rn.f32x2 %0, %1, %2, %0;" : "+l"(d) : "l"(a), "l"(b));
}
__device__ __forceinline__ ull fma2v(ull a, ull b, ull c) {
    ull r; asm("fma.rn.f32x2 %0, %1, %2, %3;" : "=l"(r) : "l"(a), "l"(b), "l"(c)); return r;
}
__device__ __forceinline__ ull mul2(ull a, ull b) {
    ull r; asm("mul.rn.f32x2 %0, %1, %2;" : "=l"(r) : "l"(a), "l"(b)); return r;
}

// GELU on 2 packed fp32 lanes: x * sigmoid(1.59577x + 0.0713548x^3)
__device__ __forceinline__ ull gelu2(ull x2) {
    ull xsq = mul2(x2, x2);
    ull t = fma2v(xsq, pack2(0.07135481627f, 0.07135481627f),
                        pack2(1.59576912161f, 1.59576912161f));
    ull y = mul2(x2, t);
    ull z = mul2(y, pack2(-1.44269504089f, -1.44269504089f));
    float zlo, zhi; unpack2(z, zlo, zhi);
    float elo, ehi;
    asm("ex2.approx.f32 %0, %1;" : "=f"(elo) : "f"(zlo));
    asm("ex2.approx.f32 %0, %1;" : "=f"(ehi) : "f"(zhi));
    float dlo = 1.0f + elo, dhi = 1.0f + ehi;
    float slo, shi;
    asm("rcp.approx.f32 %0, %1;" : "=f"(slo) : "f"(dlo));
    asm("rcp.approx.f32 %0, %1;" : "=f"(shi) : "f"(dhi));
    return mul2(x2, pack2(slo, shi));
}

__global__ __launch_bounds__(256, 3)
void fused_residual_advection(const float* __restrict__ pm25,
                              const float* __restrict__ wind,
                              const float* __restrict__ topo,
                              const float* __restrict__ w1,
                              const float* __restrict__ b1,
                              const float* __restrict__ w2,
                              const float* __restrict__ b2,
                              const float* __restrict__ wk,
                              float* __restrict__ out)
{
    extern __shared__ float smem[];
    float*  s_in     = smem;                             // [3][36][36]; phase3: dup-w table
    __half* s_feat_h = (__half*)(s_in + 3*ID*ID);        // [16][34][40] halves
    float*  s_w1t    = s_in + 3*ID*ID + (16*FD*FDPH)/2;  // [27][16]
    float*  s_b1     = s_w1t + 432;
    float*  s_b2     = s_b1 + 16;
    float*  s_wk     = s_b2 + 18;

    const int tid = threadIdx.x;
    const int b   = blockIdx.z;
    const int ty0 = blockIdx.y * TILE;
    const int tx0 = blockIdx.x * TILE;

    for (int i = tid; i < 432; i += 256) {
        int o = i / 27, j = i - o * 27;
        s_w1t[j*16 + o] = w1[i];
    }
    if (tid < 16) s_b1[tid] = b1[tid];
    else if (tid >= 32 && tid < 50) s_b2[tid - 32] = b2[tid - 32];
    else if (tid >= 64 && tid < 73) s_wk[tid - 64] = wk[tid - 64];

    const int gy0 = ty0 - 2, gx0 = tx0 - 2;
    const float* wind0 = wind + (size_t)b * 2 * Hn * Wn;
    const float* wind1 = wind0 + Hn * Wn;
    const float* topob = topo + (size_t)b * Hn * Wn;
    for (int i = tid; i < ID*ID; i += 256) {
        int ly = i / ID, lx = i - ly * ID;
        int gy = gy0 + ly, gx = gx0 + lx;
        bool ok = (gy >= 0) & (gy < Hn) & (gx >= 0) & (gx < Wn);
        size_t gidx = (size_t)gy * Wn + gx;
        s_in[0*ID*ID + i] = ok ? __ldg(wind0 + gidx) : 0.f;
        s_in[1*ID*ID + i] = ok ? __ldg(wind1 + gidx) : 0.f;
        s_in[2*ID*ID + i] = ok ? __ldg(topob + gidx) : 0.f;
    }
    __syncthreads();

    // ---- phase 2: conv1 + GELU -> fp16 feat (balanced pairs + single tail) ----
    {
        ull b1p[8];
        #pragma unroll
        for (int p = 0; p < 8; p++) b1p[p] = pack2(s_b1[2*p], s_b1[2*p + 1]);

        // main: pairs 0..511 -> pixels 0..1023
        #pragma unroll
        for (int it = 0; it < 2; it++) {
            const int pi = tid + it*256;
            const int lin = 2*pi;
            const int fy = lin / FD, fx = lin - fy * FD;   // fx even
            const bool okA = ((unsigned)(ty0 - 1 + fy) < Hn) & ((unsigned)(tx0 - 1 + fx)     < Wn);
            const bool okB = ((unsigned)(ty0 - 1 + fy) < Hn) & ((unsigned)(tx0 - 1 + fx + 1) < Wn);

            float r[3][3][4];
            #pragma unroll
            for (int c = 0; c < 3; c++)
                #pragma unroll
                for (int ky = 0; ky < 3; ky++) {
                    const float* rp = &s_in[c*ID*ID + (fy + ky)*ID + fx];
                    const float2 q0 = *(const float2*)rp;
                    const float2 q1 = *(const float2*)(rp + 2);
                    r[c][ky][0] = q0.x; r[c][ky][1] = q0.y;
                    r[c][ky][2] = q1.x; r[c][ky][3] = q1.y;
                }

            const int po = fy*FDPH + fx;
            #pragma unroll
            for (int h = 0; h < 2; h++) {
                ull aA[4], aB[4];
                #pragma unroll
                for (int p = 0; p < 4; p++) { aA[p] = b1p[4*h + p]; aB[p] = b1p[4*h + p]; }

                #pragma unroll
                for (int j = 0; j < 27; j++) {
                    const int c  = j / 9;
                    const int r9 = j - c * 9;
                    const int ky = r9 / 3, kx = r9 - ky * 3;
                    const ull vA2 = pack2(r[c][ky][kx],     r[c][ky][kx]);
                    const ull vB2 = pack2(r[c][ky][kx + 1], r[c][ky][kx + 1]);
                    const ulonglong2* wp = (const ulonglong2*)&s_w1t[j*16 + h*8];
                    const ulonglong2 w01 = wp[0], w23 = wp[1];
                    ffma2(aA[0], vA2, w01.x); ffma2(aA[1], vA2, w01.y);
                    ffma2(aA[2], vA2, w23.x); ffma2(aA[3], vA2, w23.y);
                    ffma2(aB[0], vB2, w01.x); ffma2(aB[1], vB2, w01.y);
                    ffma2(aB[2], vB2, w23.x); ffma2(aB[3], vB2, w23.y);
                }

                #pragma unroll
                for (int p = 0; p < 4; p++) {
                    const int ch = 8*h + 2*p;
                    float g0A, g1A, g0B, g1B;
                    unpack2(gelu2(aA[p]), g0A, g1A);
                    unpack2(gelu2(aB[p]), g0B, g1B);
                    g0A = okA ? g0A : 0.f; g1A = okA ? g1A : 0.f;
                    g0B = okB ? g0B : 0.f; g1B = okB ? g1B : 0.f;
                    *(__half2*)&s_feat_h[ch    *FD*FDPH + po] = __floats2half2_rn(g0A, g0B);
                    *(__half2*)&s_feat_h[(ch+1)*FD*FDPH + po] = __floats2half2_rn(g1A, g1B);
                }
            }
        }

        // tail: pixels 1024..1155 as singles over threads 0..131
        if (tid < 132) {
            const int lin = 1024 + tid;
            const int fy = lin / FD, fx = lin - fy * FD;
            const bool ok = ((unsigned)(ty0 - 1 + fy) < Hn) & ((unsigned)(tx0 - 1 + fx) < Wn);

            float r[3][3][3];
            #pragma unroll
            for (int c = 0; c < 3; c++)
                #pragma unroll
                for (int ky = 0; ky < 3; ky++) {
                    const float* rp = &s_in[c*ID*ID + (fy + ky)*ID + fx];
                    r[c][ky][0] = rp[0]; r[c][ky][1] = rp[1]; r[c][ky][2] = rp[2];
                }

            const int po = fy*FDPH + fx;
            #pragma unroll
            for (int h = 0; h < 2; h++) {
                ull aA[4];
                #pragma unroll
                for (int p = 0; p < 4; p++) aA[p] = b1p[4*h + p];
                #pragma unroll
                for (int j = 0; j < 27; j++) {
                    const int c  = j / 9;
                    const int r9 = j - c * 9;
                    const int ky = r9 / 3, kx = r9 - ky * 3;
                    const ull v2 = pack2(r[c][ky][kx], r[c][ky][kx]);
                    const ulonglong2* wp = (const ulonglong2*)&s_w1t[j*16 + h*8];
                    const ulonglong2 w01 = wp[0], w23 = wp[1];
                    ffma2(aA[0], v2, w01.x); ffma2(aA[1], v2, w01.y);
                    ffma2(aA[2], v2, w23.x); ffma2(aA[3], v2, w23.y);
                }
                #pragma unroll
                for (int p = 0; p < 4; p++) {
                    const int ch = 8*h + 2*p;
                    float g0, g1;
                    unpack2(gelu2(aA[p]), g0, g1);
                    s_feat_h[ch    *FD*FDPH + po] = __float2half_rn(ok ? g0 : 0.f);
                    s_feat_h[(ch+1)*FD*FDPH + po] = __float2half_rn(ok ? g1 : 0.f);
                }
            }
        }
    }
    __syncthreads();

    // ---- phase 3: conv2 (active taps) + bilinear; 2x2 output block/thread ----
    const int x0 = (tid & 15) * 2;   // 0..30
    const int r0 = (tid >> 4) * 2;   // 0..30
    const float* img = pm25 + (size_t)b * Hn * Wn;
    float* s_wdup = s_in;    // dead region; [j][c]{wdy,wdy,wdx,wdx} = 576 floats

    float accT[2] = {0.f, 0.f};   // row r0,   cols x0, x0+1
    float accB[2] = {0.f, 0.f};   // row r0+1
    bool first_tap = true;

    for (int k = 0; k < 9; k++) {
        const float wkv = s_wk[k];
        if (wkv == 0.0f) continue;          // uniform across block, value-exact
        const int kdy = k / 3 - 1, kdx = k - (k/3)*3 - 1;

        if (!first_tap) __syncthreads();
        first_tap = false;
        for (int i = tid; i < 144; i += 256) {
            const int c = i / 9, j = i - c * 9;
            const float wy = __ldg(&w2[(size_t)(2*k)    *144 + c*9 + j]);
            const float wx = __ldg(&w2[(size_t)(2*k + 1)*144 + c*9 + j]);
            float* p = &s_wdup[(j*16 + c)*4];
            p[0] = wy; p[1] = wy; p[2] = wx; p[3] = wx;
        }
        __syncthreads();

        const float bdy = s_b2[2*k], bdx = s_b2[2*k + 1];
        ull adyT = pack2(bdy, bdy), adyB = adyT;
        ull adxT = pack2(bdx, bdx), adxB = adxT;

        #pragma unroll
        for (int c = 0; c < 16; c++) {
            const __half* fb = s_feat_h + c*FD*FDPH + r0*FDPH + x0;
            // 4 feat rows x 4 halves; rows r0+1, r0+2 shared by both output rows
            ull P[4][3];
            #pragma unroll
            for (int ry = 0; ry < 4; ry++) {
                const __half* rp = fb + ry*FDPH;
                const __half2 hA = *(const __half2*)(rp);
                const __half2 hB = *(const __half2*)(rp + 2);
                const float2 eA = __half22float2(hA);
                const float2 eB = __half22float2(hB);
                P[ry][0] = pack2(eA.x, eA.y);
                P[ry][1] = pack2(eA.y, eB.x);
                P[ry][2] = pack2(eB.x, eB.y);
            }
            #pragma unroll
            for (int ky = 0; ky < 3; ky++) {
                #pragma unroll
                for (int kx = 0; kx < 3; kx++) {
                    const int jj = ky*3 + kx;
                    const ulonglong2 wv = *(const ulonglong2*)&s_wdup[((jj)*16 + c)*4];
                    ffma2(adyT, P[ky][kx],     wv.x);
                    ffma2(adyB, P[ky+1][kx],   wv.x);
                    ffma2(adxT, P[ky][kx],     wv.y);
                    ffma2(adxB, P[ky+1][kx],   wv.y);
                }
            }
        }

        float dyv[4], dxv[4];   // [0]=T,x0  [1]=T,x0+1  [2]=B,x0  [3]=B,x0+1
        unpack2(adyT, dyv[0], dyv[1]); unpack2(adyB, dyv[2], dyv[3]);
        unpack2(adxT, dxv[0], dxv[1]); unpack2(adxB, dxv[2], dxv[3]);

        #pragma unroll
        for (int i = 0; i < 4; i++) {
            const int gy = ty0 + r0 + (i >> 1);
            const int gx = tx0 + x0 + (i & 1);
            const float py = (float)(gy + kdy) + dyv[i];
            const float px = (float)(gx + kdx) + dxv[i];
            const float y0f = floorf(py), x0f = floorf(px);
            const float wy = py - y0f, wx = px - x0f;
            const int yy0 = (int)y0f, xx0 = (int)x0f;
            const int yy1 = yy0 + 1,  xx1 = xx0 + 1;
            const bool okY0 = (yy0 >= 0) & (yy0 < Hn);
            const bool okY1 = (yy1 >= 0) & (yy1 < Hn);
            const bool okX0 = (xx0 >= 0) & (xx0 < Wn);
            const bool okX1 = (xx1 >= 0) & (xx1 < Wn);
            const float v00 = (okY0 & okX0) ? __ldg(img + (size_t)yy0*Wn + xx0) : 0.f;
            const float v01 = (okY0 & okX1) ? __ldg(img + (size_t)yy0*Wn + xx1) : 0.f;
            const float v10 = (okY1 & okX0) ? __ldg(img + (size_t)yy1*Wn + xx0) : 0.f;
            const float v11 = (okY1 & okX1) ? __ldg(img + (size_t)yy1*Wn + xx1) : 0.f;
            const float s = v00*(1.f - wy)*(1.f - wx) + v01*(1.f - wy)*wx
                          + v10*wy*(1.f - wx)         + v11*wy*wx;
            if (i < 2) accT[i] = fmaf(wkv, s, accT[i]);
            else       accB[i - 2] = fmaf(wkv, s, accB[i - 2]);
        }
    }

    // two coalesced float2 stores
    {
        float2 oT; oT.x = accT[0]; oT.y = accT[1];
        float2 oB; oB.x = accB[0]; oB.y = accB[1];
        size_t base = (size_t)b * Hn * Wn;
        *(float2*)&out[base + (size_t)(ty0 + r0)     * Wn + (tx0 + x0)] = oT;
        *(float2*)&out[base + (size_t)(ty0 + r0 + 1) * Wn + (tx0 + x0)] = oB;
    }
}

extern "C" void kernel_launch(void* const* d_in, const int* in_sizes, int n_in,
                              void* d_out, int out_size)
{
    const float* pm25 = (const float*)d_in[0];
    const float* wind = (const float*)d_in[1];
    const float* topo = (const float*)d_in[2];
    const float* w1   = (const float*)d_in[3];
    const float* b1   = (const float*)d_in[4];
    const float* w2   = (const float*)d_in[5];
    const float* b2   = (const float*)d_in[6];
    const float* wk   = (const float*)d_in[7];
    float* out = (float*)d_out;

    const size_t smem_bytes = (size_t)SMEM_FLOATS * sizeof(float);
    cudaFuncSetAttribute(fused_residual_advection,
                         cudaFuncAttributeMaxDynamicSharedMemorySize,
                         (int)smem_bytes);

    dim3 grid(Wn / TILE, Hn / TILE, Bn);
    fused_residual_advection<<<grid, 256, smem_bytes>>>(
        pm25, wind, topo, w1, b1, w2, b2, wk, out);
}